// round 12
// baseline (speedup 1.0000x reference)
#include <cuda_runtime.h>
#include <cstdint>

// SplitMLP R11: R10 (mma.sync tf32 fc1 + register fc2) with cp.async staging.
//   - cp.async.cg 16B global->smem for day/items/W1d/W1v: no register round trip,
//     async until one wait right before the MMA barrier.
//   - raw fp32 in smem; HMMA.TF32 truncates in HW (no cvt.rna pass).
//   As[b][k] pitch 52, Ws[j][k] pitch 52: conflict-free fragment LDS (banks 20r+q).
//   4 warps: warp w owns b-rows 32w..32w+31 (2 m-tiles) x all 64 j (8 n-tiles).

#define NG 10000
#define PA 52

typedef unsigned long long ull;
typedef unsigned int uint;

#define FMA2(d, a, b, c) \
    asm("fma.rn.f32x2 %0, %1, %2, %3;" : "=l"(d) : "l"(a), "l"(b), "l"(c))
#define ADD2(d, a, b) \
    asm("add.rn.f32x2 %0, %1, %2;" : "=l"(d) : "l"(a), "l"(b))
#define PACK2(d, x) \
    asm("mov.b64 %0, {%1, %1};" : "=l"(d) : "f"(x))
#define UNPACK2(lo, hi, v) \
    asm("mov.b64 {%0, %1}, %2;" : "=f"(lo), "=f"(hi) : "l"(v))

#define CPASYNC16(dst_u32, src_gptr) \
    asm volatile("cp.async.cg.shared.global [%0], [%1], 16;" \
                 :: "r"(dst_u32), "l"(src_gptr) : "memory")

__device__ __forceinline__ uint smem_u32(const void* p) {
    uint a;
    asm("{ .reg .u64 t; cvta.to.shared.u64 t, %1; cvt.u32.u64 %0, t; }" : "=r"(a) : "l"(p));
    return a;
}

__device__ __forceinline__ void mma_tf32(float& d0, float& d1, float& d2, float& d3,
                                         uint a0, uint a1, uint a2, uint a3,
                                         uint b0, uint b1) {
    asm volatile(
        "mma.sync.aligned.m16n8k8.row.col.f32.tf32.tf32.f32 "
        "{%0,%1,%2,%3}, {%4,%5,%6,%7}, {%8,%9}, {%0,%1,%2,%3};"
        : "+f"(d0), "+f"(d1), "+f"(d2), "+f"(d3)
        : "r"(a0), "r"(a1), "r"(a2), "r"(a3), "r"(b0), "r"(b1));
}

__device__ __forceinline__ ull bfly_add2(ull v, int m) {
    float lo, hi;
    UNPACK2(lo, hi, v);
    uint lo2 = __shfl_xor_sync(0xffffffffu, __float_as_uint(lo), m);
    uint hi2 = __shfl_xor_sync(0xffffffffu, __float_as_uint(hi), m);
    ull o;
    asm("mov.b64 %0, {%1, %2};" : "=l"(o) : "r"(lo2), "r"(hi2));
    ull r;
    ADD2(r, v, o);
    return r;
}

__global__ __launch_bounds__(128)
void splitmlp_kernel(const float* __restrict__ day,
                     const float* __restrict__ items,
                     const float* __restrict__ W1d,
                     const float* __restrict__ W1v,
                     const float* __restrict__ b1,
                     const float* __restrict__ W2,
                     const float* __restrict__ b2,
                     float* __restrict__ out)
{
    __shared__ __align__(16) float As[128 * PA];   // [b][k], k 0..47 valid
    __shared__ __align__(16) float Ws[64 * PA];    // [j][k]
    __shared__ __align__(16) float W2sT[64 * 4];   // [j][o]
    __shared__ __align__(16) float b1s[64];
    __shared__ __align__(16) float b2s[4];

    const int g = blockIdx.x;
    const int t = threadIdx.x;
    const int lane = t & 31, w = t >> 5;

    const uint asb = smem_u32(As);
    const uint wsb = smem_u32(Ws);

    // ================= Async staging (raw fp32; HW truncates to tf32) ==========
    // items[b][g][v] -> As[b][16+4q]   (DRAM-heavy: issue first)
    {
        const float4* src = (const float4*)items;  // [b][NG*8]
        #pragma unroll
        for (int i = 0; i < 8; i++) {
            int idx = t + i * 128;
            int b = idx >> 3, q = idx & 7;
            CPASYNC16(asb + (uint)(b * PA + 16 + 4 * q) * 4u,
                      src + (size_t)b * (NG * 8) + (size_t)g * 8 + q);
        }
    }
    // W1v[g][j][v] -> Ws[j][16+4vq]
    {
        const float4* src = (const float4*)W1v;    // g*512 + j*8 + vq
        #pragma unroll
        for (int i = 0; i < 4; i++) {
            int idx = t + i * 128;
            int j = idx >> 3, vq = idx & 7;
            CPASYNC16(wsb + (uint)(j * PA + 16 + 4 * vq) * 4u,
                      src + (size_t)g * 512 + j * 8 + vq);
        }
    }
    // W1d[g][j][c] -> Ws[j][4cq]
    {
        const float4* src = (const float4*)W1d;    // g*256 + j*4 + cq
        #pragma unroll
        for (int i = 0; i < 2; i++) {
            int idx = t + i * 128;
            int j = idx >> 2, cq = idx & 3;
            CPASYNC16(wsb + (uint)(j * PA + 4 * cq) * 4u,
                      src + (size_t)g * 256 + j * 4 + cq);
        }
    }
    // day[b][c] -> As[b][4q]   (L2-resident after first wave)
    {
        const float4* src = (const float4*)day;    // 512 float4
        #pragma unroll
        for (int i = 0; i < 4; i++) {
            int idx = t + i * 128;
            int b = idx >> 2, q = idx & 3;
            CPASYNC16(asb + (uint)(b * PA + 4 * q) * 4u, src + idx);
        }
    }
    asm volatile("cp.async.commit_group;" ::: "memory");

    // W2 transpose + biases via regular ld/st (small, overlaps with cp.async)
    if (t < 64) {
        int o = t >> 4, jq = t & 15;
        float4 v = ((const float4*)W2)[(size_t)g * 64 + o * 16 + jq];
        W2sT[(4 * jq + 0) * 4 + o] = v.x;
        W2sT[(4 * jq + 1) * 4 + o] = v.y;
        W2sT[(4 * jq + 2) * 4 + o] = v.z;
        W2sT[(4 * jq + 3) * 4 + o] = v.w;
    } else {
        b1s[t - 64] = b1[(size_t)g * 64 + (t - 64)];
    }
    if (t < 4) b2s[t] = b2[(size_t)g * 4 + t];

    asm volatile("cp.async.wait_group 0;" ::: "memory");
    __syncthreads();

    // ================= fc1: mma.sync tf32 =================
    const int r = lane >> 2, q = lane & 3;
    const uint* Au = (const uint*)As;
    const uint* Wu = (const uint*)Ws;
    const int m0 = w * 32;            // warp's first b-row; m-tiles at m0, m0+16

    float d[2][8][4];
    #pragma unroll
    for (int mt = 0; mt < 2; mt++)
        #pragma unroll
        for (int nt = 0; nt < 8; nt++)
            #pragma unroll
            for (int c = 0; c < 4; c++) d[mt][nt][c] = 0.0f;

    #pragma unroll
    for (int ks = 0; ks < 6; ks++) {
        const int k0 = ks * 8;
        uint bf[8][2];
        #pragma unroll
        for (int nt = 0; nt < 8; nt++) {
            bf[nt][0] = Wu[(nt * 8 + r) * PA + k0 + q];
            bf[nt][1] = Wu[(nt * 8 + r) * PA + k0 + 4 + q];
        }
        #pragma unroll
        for (int mt = 0; mt < 2; mt++) {
            const int row = m0 + mt * 16 + r;
            uint a0 = Au[row * PA + k0 + q];
            uint a1 = Au[(row + 8) * PA + k0 + q];
            uint a2 = Au[row * PA + k0 + 4 + q];
            uint a3 = Au[(row + 8) * PA + k0 + 4 + q];
            #pragma unroll
            for (int nt = 0; nt < 8; nt++)
                mma_tf32(d[mt][nt][0], d[mt][nt][1], d[mt][nt][2], d[mt][nt][3],
                         a0, a1, a2, a3, bf[nt][0], bf[nt][1]);
        }
    }

    // ================= bias + relu + fc2 (registers) =================
    ull y01[4], y23[4];
    #pragma unroll
    for (int i = 0; i < 4; i++) { y01[i] = 0ULL; y23[i] = 0ULL; }

    #pragma unroll
    for (int nt = 0; nt < 8; nt++) {
        const int j0 = nt * 8 + 2 * q;
        float2 bb = *(const float2*)&b1s[j0];
        ulonglong2 wj0 = *(const ulonglong2*)&W2sT[j0 * 4];
        ulonglong2 wj1 = *(const ulonglong2*)&W2sT[(j0 + 1) * 4];
        #pragma unroll
        for (int mt = 0; mt < 2; mt++) {
            {
                float h0 = fmaxf(d[mt][nt][0] + bb.x, 0.0f);
                float h1 = fmaxf(d[mt][nt][1] + bb.y, 0.0f);
                ull h;
                PACK2(h, h0);
                FMA2(y01[mt * 2], h, wj0.x, y01[mt * 2]);
                FMA2(y23[mt * 2], h, wj0.y, y23[mt * 2]);
                PACK2(h, h1);
                FMA2(y01[mt * 2], h, wj1.x, y01[mt * 2]);
                FMA2(y23[mt * 2], h, wj1.y, y23[mt * 2]);
            }
            {
                float h0 = fmaxf(d[mt][nt][2] + bb.x, 0.0f);
                float h1 = fmaxf(d[mt][nt][3] + bb.y, 0.0f);
                ull h;
                PACK2(h, h0);
                FMA2(y01[mt * 2 + 1], h, wj0.x, y01[mt * 2 + 1]);
                FMA2(y23[mt * 2 + 1], h, wj0.y, y23[mt * 2 + 1]);
                PACK2(h, h1);
                FMA2(y01[mt * 2 + 1], h, wj1.x, y01[mt * 2 + 1]);
                FMA2(y23[mt * 2 + 1], h, wj1.y, y23[mt * 2 + 1]);
            }
        }
    }

    // quad reduction (lanes 4r..4r+3 share rows)
    #pragma unroll
    for (int i = 0; i < 4; i++) {
        y01[i] = bfly_add2(y01[i], 1);
        y01[i] = bfly_add2(y01[i], 2);
        y23[i] = bfly_add2(y23[i], 1);
        y23[i] = bfly_add2(y23[i], 2);
    }

    // lane q writes row-set q: b = m0 + (q>>1)*16 + (q&1)*8 + r
    {
        ull s01 = (q == 0) ? y01[0] : (q == 1) ? y01[1] : (q == 2) ? y01[2] : y01[3];
        ull s23 = (q == 0) ? y23[0] : (q == 1) ? y23[1] : (q == 2) ? y23[2] : y23[3];
        ull bb01 = *(const ull*)&b2s[0];
        ull bb23 = *(const ull*)&b2s[2];
        ADD2(s01, s01, bb01);
        ADD2(s23, s23, bb23);
        float4 res;
        UNPACK2(res.x, res.y, s01);
        UNPACK2(res.z, res.w, s23);
        const int b = m0 + (q >> 1) * 16 + (q & 1) * 8 + r;
        *(float4*)&out[(size_t)b * (NG * 4) + (size_t)g * 4] = res;
    }
}

extern "C" void kernel_launch(void* const* d_in, const int* in_sizes, int n_in,
                              void* d_out, int out_size)
{
    const float* day   = (const float*)d_in[0];
    const float* items = (const float*)d_in[1];
    const float* W1d   = (const float*)d_in[2];
    const float* W1v   = (const float*)d_in[3];
    const float* b1    = (const float*)d_in[4];
    const float* W2    = (const float*)d_in[5];
    const float* b2    = (const float*)d_in[6];
    float* out = (float*)d_out;

    splitmlp_kernel<<<NG, 128>>>(day, items, W1d, W1v, b1, W2, b2, out);
}

// round 14
// speedup vs baseline: 1.2512x; 1.2512x over previous
#include <cuda_runtime.h>
#include <cstdint>

// SplitMLP R13: persistent multi-group CTA + double-buffered cp.async pipeline.
//   2500 CTAs x 4 groups (g = i*2500 + bx). fc1 = mma.sync tf32 m16n8k8, fc2 in regs.
//   dayS[b][c]   pitch 20, staged ONCE per CTA      (frag banks 20r+q: conflict-free)
//   itS[2][b][v] pitch 36, double-buffered cp.async (frag banks  4r+q: conflict-free)
//   WsS[2][j][k] pitch 52, double-buffered cp.async (frag banks 20r+q: conflict-free)
//   W2sT/b1/b2 double-buffered via LDG->reg during compute, STS after.

#define NG   10000
#define NCTA 2500
#define GPC  4
#define PDAY 20
#define PIT  36
#define PW   52

// float offsets in dynamic smem
#define F_DAY 0            // 128*20 = 2560
#define F_IT  2560         // 2 * (128*36=4608)
#define F_WS  11776        // 2 * (64*52=3328)
#define F_W2  18432        // 2 * 256
#define F_B1  18944        // 2 * 64
#define F_B2  19072        // 2 * 8
#define SMEM_FLOATS 19088
#define SMEM_BYTES (SMEM_FLOATS * 4)

typedef unsigned long long ull;
typedef unsigned int uint;

#define FMA2(d, a, b, c) \
    asm("fma.rn.f32x2 %0, %1, %2, %3;" : "=l"(d) : "l"(a), "l"(b), "l"(c))
#define ADD2(d, a, b) \
    asm("add.rn.f32x2 %0, %1, %2;" : "=l"(d) : "l"(a), "l"(b))
#define PACK2(d, x) \
    asm("mov.b64 %0, {%1, %1};" : "=l"(d) : "f"(x))
#define UNPACK2(lo, hi, v) \
    asm("mov.b64 {%0, %1}, %2;" : "=f"(lo), "=f"(hi) : "l"(v))
#define CPASYNC16(dst_u32, src_gptr) \
    asm volatile("cp.async.cg.shared.global [%0], [%1], 16;" \
                 :: "r"(dst_u32), "l"(src_gptr) : "memory")

__device__ __forceinline__ uint smem_u32(const void* p) {
    uint a;
    asm("{ .reg .u64 t; cvta.to.shared.u64 t, %1; cvt.u32.u64 %0, t; }" : "=r"(a) : "l"(p));
    return a;
}

__device__ __forceinline__ void mma_tf32(float& d0, float& d1, float& d2, float& d3,
                                         uint a0, uint a1, uint a2, uint a3,
                                         uint b0, uint b1) {
    asm volatile(
        "mma.sync.aligned.m16n8k8.row.col.f32.tf32.tf32.f32 "
        "{%0,%1,%2,%3}, {%4,%5,%6,%7}, {%8,%9}, {%0,%1,%2,%3};"
        : "+f"(d0), "+f"(d1), "+f"(d2), "+f"(d3)
        : "r"(a0), "r"(a1), "r"(a2), "r"(a3), "r"(b0), "r"(b1));
}

__device__ __forceinline__ ull bfly_add2(ull v, int m) {
    float lo, hi;
    UNPACK2(lo, hi, v);
    uint lo2 = __shfl_xor_sync(0xffffffffu, __float_as_uint(lo), m);
    uint hi2 = __shfl_xor_sync(0xffffffffu, __float_as_uint(hi), m);
    ull o;
    asm("mov.b64 %0, {%1, %2};" : "=l"(o) : "r"(lo2), "r"(hi2));
    ull r;
    ADD2(r, v, o);
    return r;
}

__global__ __launch_bounds__(128)
void splitmlp_kernel(const float* __restrict__ day,
                     const float* __restrict__ items,
                     const float* __restrict__ W1d,
                     const float* __restrict__ W1v,
                     const float* __restrict__ b1,
                     const float* __restrict__ W2,
                     const float* __restrict__ b2,
                     float* __restrict__ out)
{
    extern __shared__ __align__(16) float smem[];
    const int bx = blockIdx.x;
    const int t  = threadIdx.x;
    const int lane = t & 31, w = t >> 5;
    const int r = lane >> 2, q = lane & 3;
    const int m0 = w * 32;

    const uint sb = smem_u32(smem);
    const uint dayb = sb + F_DAY * 4u;

    // ---- helper: issue cp.async prefetch of group g into buffer `buf` ----
    auto issue_group = [&](int buf, int g) {
        const uint itb = sb + (F_IT + buf * 4608) * 4u;
        const uint wsb = sb + (F_WS + buf * 3328) * 4u;
        {   // items: 1024 float4
            const float4* src = (const float4*)items + (size_t)g * 8;
            #pragma unroll
            for (int i = 0; i < 8; i++) {
                int idx = t + i * 128;
                int b = idx >> 3, qq = idx & 7;
                CPASYNC16(itb + (uint)(b * PIT + 4 * qq) * 4u,
                          src + (size_t)b * (NG * 8) + qq);
            }
        }
        {   // W1v: 512 float4 -> Ws[j][16+4vq]
            const float4* src = (const float4*)W1v + (size_t)g * 512;
            #pragma unroll
            for (int i = 0; i < 4; i++) {
                int idx = t + i * 128;
                int j = idx >> 3, vq = idx & 7;
                CPASYNC16(wsb + (uint)(j * PW + 16 + 4 * vq) * 4u, src + j * 8 + vq);
            }
        }
        {   // W1d: 256 float4 -> Ws[j][4cq]
            const float4* src = (const float4*)W1d + (size_t)g * 256;
            #pragma unroll
            for (int i = 0; i < 2; i++) {
                int idx = t + i * 128;
                int j = idx >> 2, cq = idx & 3;
                CPASYNC16(wsb + (uint)(j * PW + 4 * cq) * 4u, src + j * 4 + cq);
            }
        }
    };

    // ---- prologue: day (once) + group 0 ----
    {
        const float4* src = (const float4*)day;
        #pragma unroll
        for (int i = 0; i < 4; i++) {
            int idx = t + i * 128;
            int b = idx >> 2, qq = idx & 3;
            CPASYNC16(dayb + (uint)(b * PDAY + 4 * qq) * 4u, src + idx);
        }
    }
    issue_group(0, bx);
    asm volatile("cp.async.commit_group;" ::: "memory");

    // small tensors for group 0 (LDG -> regs -> STS; prologue only)
    float4 w2reg;
    float b1reg = 0.0f, b2reg = 0.0f;
    {
        int g0 = bx;
        if (t < 64) {
            int o = t >> 4, jq = t & 15;
            w2reg = ((const float4*)W2)[(size_t)g0 * 64 + o * 16 + jq];
        } else {
            b1reg = b1[(size_t)g0 * 64 + (t - 64)];
        }
        if (t < 4) b2reg = b2[(size_t)g0 * 4 + t];
        float* W2sT = smem + F_W2;
        float* b1s  = smem + F_B1;
        float* b2s  = smem + F_B2;
        if (t < 64) {
            int o = t >> 4, jq = t & 15;
            W2sT[(4 * jq + 0) * 4 + o] = w2reg.x;
            W2sT[(4 * jq + 1) * 4 + o] = w2reg.y;
            W2sT[(4 * jq + 2) * 4 + o] = w2reg.z;
            W2sT[(4 * jq + 3) * 4 + o] = w2reg.w;
        } else {
            b1s[t - 64] = b1reg;
        }
        if (t < 4) b2s[t] = b2reg;
    }

    // ---- main pipeline ----
    for (int i = 0; i < GPC; i++) {
        const int buf = i & 1;
        const int g = i * NCTA + bx;
        const bool has_next = (i + 1 < GPC);

        asm volatile("cp.async.wait_group 0;" ::: "memory");
        __syncthreads();

        if (has_next) {
            issue_group(buf ^ 1, g + NCTA);
            asm volatile("cp.async.commit_group;" ::: "memory");
            int gn = g + NCTA;
            if (t < 64) {
                int o = t >> 4, jq = t & 15;
                w2reg = ((const float4*)W2)[(size_t)gn * 64 + o * 16 + jq];
            } else {
                b1reg = b1[(size_t)gn * 64 + (t - 64)];
            }
            if (t < 4) b2reg = b2[(size_t)gn * 4 + t];
        }

        // ================= fc1: mma.sync tf32 =================
        const uint* dayU = (const uint*)(smem + F_DAY);
        const uint* itU  = (const uint*)(smem + F_IT + buf * 4608);
        const uint* Wu   = (const uint*)(smem + F_WS + buf * 3328);

        float d[2][8][4];
        #pragma unroll
        for (int mt = 0; mt < 2; mt++)
            #pragma unroll
            for (int nt = 0; nt < 8; nt++)
                #pragma unroll
                for (int c = 0; c < 4; c++) d[mt][nt][c] = 0.0f;

        #pragma unroll
        for (int ks = 0; ks < 6; ks++) {
            const int k0 = ks * 8;
            uint bf[8][2];
            #pragma unroll
            for (int nt = 0; nt < 8; nt++) {
                bf[nt][0] = Wu[(nt * 8 + r) * PW + k0 + q];
                bf[nt][1] = Wu[(nt * 8 + r) * PW + k0 + 4 + q];
            }
            const uint* Ap  = (ks < 2) ? dayU : itU;
            const int apit  = (ks < 2) ? PDAY : PIT;
            const int ak    = (ks < 2) ? k0 : (k0 - 16);
            #pragma unroll
            for (int mt = 0; mt < 2; mt++) {
                const int row = m0 + mt * 16 + r;
                uint a0 = Ap[row * apit + ak + q];
                uint a1 = Ap[(row + 8) * apit + ak + q];
                uint a2 = Ap[row * apit + ak + 4 + q];
                uint a3 = Ap[(row + 8) * apit + ak + 4 + q];
                #pragma unroll
                for (int nt = 0; nt < 8; nt++)
                    mma_tf32(d[mt][nt][0], d[mt][nt][1], d[mt][nt][2], d[mt][nt][3],
                             a0, a1, a2, a3, bf[nt][0], bf[nt][1]);
            }
        }

        // ================= bias + relu + fc2 (registers) =================
        const float* W2sT = smem + F_W2 + buf * 256;
        const float* b1s  = smem + F_B1 + buf * 64;
        const float* b2s  = smem + F_B2 + buf * 8;

        ull y01[4], y23[4];
        #pragma unroll
        for (int ii = 0; ii < 4; ii++) { y01[ii] = 0ULL; y23[ii] = 0ULL; }

        #pragma unroll
        for (int nt = 0; nt < 8; nt++) {
            const int j0 = nt * 8 + 2 * q;
            float2 bb = *(const float2*)&b1s[j0];
            ulonglong2 wj0 = *(const ulonglong2*)&W2sT[j0 * 4];
            ulonglong2 wj1 = *(const ulonglong2*)&W2sT[(j0 + 1) * 4];
            #pragma unroll
            for (int mt = 0; mt < 2; mt++) {
                {
                    float h0 = fmaxf(d[mt][nt][0] + bb.x, 0.0f);
                    float h1 = fmaxf(d[mt][nt][1] + bb.y, 0.0f);
                    ull h;
                    PACK2(h, h0);
                    FMA2(y01[mt * 2], h, wj0.x, y01[mt * 2]);
                    FMA2(y23[mt * 2], h, wj0.y, y23[mt * 2]);
                    PACK2(h, h1);
                    FMA2(y01[mt * 2], h, wj1.x, y01[mt * 2]);
                    FMA2(y23[mt * 2], h, wj1.y, y23[mt * 2]);
                }
                {
                    float h0 = fmaxf(d[mt][nt][2] + bb.x, 0.0f);
                    float h1 = fmaxf(d[mt][nt][3] + bb.y, 0.0f);
                    ull h;
                    PACK2(h, h0);
                    FMA2(y01[mt * 2 + 1], h, wj0.x, y01[mt * 2 + 1]);
                    FMA2(y23[mt * 2 + 1], h, wj0.y, y23[mt * 2 + 1]);
                    PACK2(h, h1);
                    FMA2(y01[mt * 2 + 1], h, wj1.x, y01[mt * 2 + 1]);
                    FMA2(y23[mt * 2 + 1], h, wj1.y, y23[mt * 2 + 1]);
                }
            }
        }

        #pragma unroll
        for (int ii = 0; ii < 4; ii++) {
            y01[ii] = bfly_add2(y01[ii], 1);
            y01[ii] = bfly_add2(y01[ii], 2);
            y23[ii] = bfly_add2(y23[ii], 1);
            y23[ii] = bfly_add2(y23[ii], 2);
        }

        {
            ull s01 = (q == 0) ? y01[0] : (q == 1) ? y01[1] : (q == 2) ? y01[2] : y01[3];
            ull s23 = (q == 0) ? y23[0] : (q == 1) ? y23[1] : (q == 2) ? y23[2] : y23[3];
            ull bb01 = *(const ull*)&b2s[0];
            ull bb23 = *(const ull*)&b2s[2];
            ADD2(s01, s01, bb01);
            ADD2(s23, s23, bb23);
            float4 res;
            UNPACK2(res.x, res.y, s01);
            UNPACK2(res.z, res.w, s23);
            const int b = m0 + (q >> 1) * 16 + (q & 1) * 8 + r;
            *(float4*)&out[(size_t)b * (NG * 4) + (size_t)g * 4] = res;
        }

        // store small tensors for next group into other buffer
        if (has_next) {
            float* W2n = smem + F_W2 + (buf ^ 1) * 256;
            float* b1n = smem + F_B1 + (buf ^ 1) * 64;
            float* b2n = smem + F_B2 + (buf ^ 1) * 8;
            if (t < 64) {
                int o = t >> 4, jq = t & 15;
                W2n[(4 * jq + 0) * 4 + o] = w2reg.x;
                W2n[(4 * jq + 1) * 4 + o] = w2reg.y;
                W2n[(4 * jq + 2) * 4 + o] = w2reg.z;
                W2n[(4 * jq + 3) * 4 + o] = w2reg.w;
            } else {
                b1n[t - 64] = b1reg;
            }
            if (t < 4) b2n[t] = b2reg;
        }
    }
}

extern "C" void kernel_launch(void* const* d_in, const int* in_sizes, int n_in,
                              void* d_out, int out_size)
{
    const float* day   = (const float*)d_in[0];
    const float* items = (const float*)d_in[1];
    const float* W1d   = (const float*)d_in[2];
    const float* W1v   = (const float*)d_in[3];
    const float* b1    = (const float*)d_in[4];
    const float* W2    = (const float*)d_in[5];
    const float* b2    = (const float*)d_in[6];
    float* out = (float*)d_out;

    cudaFuncSetAttribute(splitmlp_kernel,
                         cudaFuncAttributeMaxDynamicSharedMemorySize, SMEM_BYTES);
    splitmlp_kernel<<<NCTA, 128, SMEM_BYTES>>>(day, items, W1d, W1v, b1, W2, b2, out);
}